// round 1
// baseline (speedup 1.0000x reference)
#include <cuda_runtime.h>

typedef unsigned long long ull;

#define NSTEP   128
#define BATCH   8192
#define HID     128
#define BC      32
#define NTHREADS 256

#define HS 34                      // padded state row stride, layout [k][r]
#define OFF_W0   0                 // W_hh0^T  [k][j]
#define OFF_W1A  (128*128)         // W_ih1^T
#define OFF_W1B  (2*128*128)       // W_hh1^T
#define OFF_H0   (3*128*128)       // h0 state [k][r], stride HS
#define OFF_H1   (OFF_H0 + 128*HS)
#define OFF_BIT  (OFF_H1 + 128*HS)
#define SMEM_FLOATS (OFF_BIT + 32)
#define SMEM_BYTES  (SMEM_FLOATS * 4)   // 231552 B <= 227KB limit

__device__ __forceinline__ ull pk2(float x, float y) {
    ull r; asm("mov.b64 %0, {%1,%2};" : "=l"(r) : "f"(x), "f"(y)); return r;
}
__device__ __forceinline__ void upk2(ull v, float &x, float &y) {
    asm("mov.b64 {%0,%1}, %2;" : "=f"(x), "=f"(y) : "l"(v));
}
__device__ __forceinline__ void fma2(ull &d, ull a, ull b) {
    asm("fma.rn.f32x2 %0, %1, %2, %0;" : "+l"(d) : "l"(a), "l"(b));
}

__global__ void __launch_bounds__(NTHREADS, 1)
rnn_wf_kernel(const float* __restrict__ samples,
              const float* __restrict__ W_ih0, const float* __restrict__ b_ih0,
              const float* __restrict__ W_hh0, const float* __restrict__ b_hh0,
              const float* __restrict__ W_ih1, const float* __restrict__ b_ih1,
              const float* __restrict__ W_hh1, const float* __restrict__ b_hh1,
              const float* __restrict__ W_dense, const float* __restrict__ b_dense,
              float* __restrict__ out)
{
    extern __shared__ float sm[];
    float* sW0  = sm + OFF_W0;
    float* sW1a = sm + OFF_W1A;
    float* sW1b = sm + OFF_W1B;
    float* sH0  = sm + OFF_H0;
    float* sH1  = sm + OFF_H1;
    int*   sBit = (int*)(sm + OFF_BIT);

    const int tid = threadIdx.x;

    // ---- load weights transposed into SMEM: sW[k][j] = W[j][k] ----
    for (int idx = tid; idx < 128*128; idx += NTHREADS) {
        int j = idx >> 7, k = idx & 127;
        sW0 [k*128 + j] = W_hh0[idx];
        sW1a[k*128 + j] = W_ih1[idx];
        sW1b[k*128 + j] = W_hh1[idx];
    }
    for (int idx = tid; idx < 128*HS; idx += NTHREADS) { sH0[idx] = 0.f; sH1[idx] = 0.f; }
    if (tid < BC) sBit[tid] = 2;   // 2 == "t=0: zero input" selector

    // ---- GEMM thread mapping: warp covers 8 rows x 64 cols, thread 4r x 4c ----
    const int lane = tid & 31, wid = tid >> 5;
    const int wr = wid >> 1, wc = wid & 1;
    const int rt = lane >> 4, ct = lane & 15;
    const int r0 = wr*8 + rt*4;          // rows r0..r0+3 (as pairs r0/r0+1, r0+2/r0+3)
    const int c0 = wc*64 + ct*4;         // cols c0..c0+3

    // per-thread constant vectors for its 4 output cols
    float cs0[4], cs1[4], cs2[4], bs1[4];
#pragma unroll
    for (int c = 0; c < 4; ++c) {
        int j = c0 + c;
        float bb = b_ih0[j] + b_hh0[j];
        cs2[c] = bb;                       // prev bit == none (t=0, x=0)
        cs0[c] = bb + W_ih0[j*2 + 0];      // prev bit == 0
        cs1[c] = bb + W_ih0[j*2 + 1];      // prev bit == 1
        bs1[c] = b_ih1[j] + b_hh1[j];
    }

    // dense-phase mapping: 8 threads per batch row
    const int drow = tid >> 3, dsub = tid & 7;
    const int bidx = blockIdx.x * BC + drow;
    float wd0[16], wd1[16];
#pragma unroll
    for (int i = 0; i < 16; ++i) {
        wd0[i] = W_dense[dsub*16 + i];
        wd1[i] = W_dense[128 + dsub*16 + i];
    }
    const float bd0 = b_dense[0], bd1 = b_dense[1];
    float lp = 0.f;

    __syncthreads();

    for (int t = 0; t < NSTEP; ++t) {
        // prefetch this step's sampled bit (used only at the dense phase)
        float s1 = 0.f;
        if (dsub == 0) s1 = __ldg(&samples[(t*BATCH + bidx)*2 + 1]);

        ull a0[4], a1[4];

        // ================= phase A: h0' = tanh(h0 @ Whh0^T + csel(bit_prev)) =====
        {
            int bA = sBit[r0+0], bB = sBit[r0+1], bC = sBit[r0+2], bD = sBit[r0+3];
#pragma unroll
            for (int c = 0; c < 4; ++c) {
                float vA = (bA==0) ? cs0[c] : ((bA==1) ? cs1[c] : cs2[c]);
                float vB = (bB==0) ? cs0[c] : ((bB==1) ? cs1[c] : cs2[c]);
                float vC = (bC==0) ? cs0[c] : ((bC==1) ? cs1[c] : cs2[c]);
                float vD = (bD==0) ? cs0[c] : ((bD==1) ? cs1[c] : cs2[c]);
                a0[c] = pk2(vA, vB);
                a1[c] = pk2(vC, vD);
            }
            const float* hp = sH0 + r0;
            const float* wp = sW0 + c0;
#pragma unroll 4
            for (int k = 0; k < 128; k += 2) {
                ull ha0 = *(const ull*)(hp + k*HS);
                ull ha1 = *(const ull*)(hp + k*HS + 2);
                ull hb0 = *(const ull*)(hp + (k+1)*HS);
                ull hb1 = *(const ull*)(hp + (k+1)*HS + 2);
                float4 wa = *(const float4*)(wp + k*128);
                float4 wb = *(const float4*)(wp + (k+1)*128);
                ull w;
                w = pk2(wa.x, wa.x); fma2(a0[0], ha0, w); fma2(a1[0], ha1, w);
                w = pk2(wa.y, wa.y); fma2(a0[1], ha0, w); fma2(a1[1], ha1, w);
                w = pk2(wa.z, wa.z); fma2(a0[2], ha0, w); fma2(a1[2], ha1, w);
                w = pk2(wa.w, wa.w); fma2(a0[3], ha0, w); fma2(a1[3], ha1, w);
                w = pk2(wb.x, wb.x); fma2(a0[0], hb0, w); fma2(a1[0], hb1, w);
                w = pk2(wb.y, wb.y); fma2(a0[1], hb0, w); fma2(a1[1], hb1, w);
                w = pk2(wb.z, wb.z); fma2(a0[2], hb0, w); fma2(a1[2], hb1, w);
                w = pk2(wb.w, wb.w); fma2(a0[3], hb0, w); fma2(a1[3], hb1, w);
            }
        }
        __syncthreads();   // all reads of old sH0 complete
#pragma unroll
        for (int c = 0; c < 4; ++c) {
            float x, y;
            upk2(a0[c], x, y);
            *(ull*)(sH0 + (c0+c)*HS + r0)     = pk2(tanhf(x), tanhf(y));
            upk2(a1[c], x, y);
            *(ull*)(sH0 + (c0+c)*HS + r0 + 2) = pk2(tanhf(x), tanhf(y));
        }
        __syncthreads();   // new sH0 visible

        // ===== phase B: h1' = tanh(h0' @ Wih1^T + h1 @ Whh1^T + bias1) ==========
#pragma unroll
        for (int c = 0; c < 4; ++c) { a0[c] = pk2(bs1[c], bs1[c]); a1[c] = a0[c]; }
        {
            const float* h0p = sH0 + r0;
            const float* h1p = sH1 + r0;
            const float* wap = sW1a + c0;
            const float* wbp = sW1b + c0;
#pragma unroll 2
            for (int k = 0; k < 128; k += 2) {
                ull p00 = *(const ull*)(h0p + k*HS);
                ull p01 = *(const ull*)(h0p + k*HS + 2);
                ull p10 = *(const ull*)(h1p + k*HS);
                ull p11 = *(const ull*)(h1p + k*HS + 2);
                ull q00 = *(const ull*)(h0p + (k+1)*HS);
                ull q01 = *(const ull*)(h0p + (k+1)*HS + 2);
                ull q10 = *(const ull*)(h1p + (k+1)*HS);
                ull q11 = *(const ull*)(h1p + (k+1)*HS + 2);
                float4 wa = *(const float4*)(wap + k*128);
                float4 wb = *(const float4*)(wbp + k*128);
                float4 wcc = *(const float4*)(wap + (k+1)*128);
                float4 wdd = *(const float4*)(wbp + (k+1)*128);
                ull w;
                w = pk2(wa.x, wa.x);  fma2(a0[0], p00, w); fma2(a1[0], p01, w);
                w = pk2(wa.y, wa.y);  fma2(a0[1], p00, w); fma2(a1[1], p01, w);
                w = pk2(wa.z, wa.z);  fma2(a0[2], p00, w); fma2(a1[2], p01, w);
                w = pk2(wa.w, wa.w);  fma2(a0[3], p00, w); fma2(a1[3], p01, w);
                w = pk2(wb.x, wb.x);  fma2(a0[0], p10, w); fma2(a1[0], p11, w);
                w = pk2(wb.y, wb.y);  fma2(a0[1], p10, w); fma2(a1[1], p11, w);
                w = pk2(wb.z, wb.z);  fma2(a0[2], p10, w); fma2(a1[2], p11, w);
                w = pk2(wb.w, wb.w);  fma2(a0[3], p10, w); fma2(a1[3], p11, w);
                w = pk2(wcc.x, wcc.x); fma2(a0[0], q00, w); fma2(a1[0], q01, w);
                w = pk2(wcc.y, wcc.y); fma2(a0[1], q00, w); fma2(a1[1], q01, w);
                w = pk2(wcc.z, wcc.z); fma2(a0[2], q00, w); fma2(a1[2], q01, w);
                w = pk2(wcc.w, wcc.w); fma2(a0[3], q00, w); fma2(a1[3], q01, w);
                w = pk2(wdd.x, wdd.x); fma2(a0[0], q10, w); fma2(a1[0], q11, w);
                w = pk2(wdd.y, wdd.y); fma2(a0[1], q10, w); fma2(a1[1], q11, w);
                w = pk2(wdd.z, wdd.z); fma2(a0[2], q10, w); fma2(a1[2], q11, w);
                w = pk2(wdd.w, wdd.w); fma2(a0[3], q10, w); fma2(a1[3], q11, w);
            }
        }
        __syncthreads();   // all reads of old sH1 complete
#pragma unroll
        for (int c = 0; c < 4; ++c) {
            float x, y;
            upk2(a0[c], x, y);
            *(ull*)(sH1 + (c0+c)*HS + r0)     = pk2(tanhf(x), tanhf(y));
            upk2(a1[c], x, y);
            *(ull*)(sH1 + (c0+c)*HS + r0 + 2) = pk2(tanhf(x), tanhf(y));
        }
        __syncthreads();   // new sH1 visible

        // ===== dense + log-softmax + accumulate =================================
        {
            float p0 = 0.f, p1 = 0.f;
            const float* hp = sH1 + drow;
#pragma unroll
            for (int i = 0; i < 16; ++i) {
                float hv = hp[(dsub*16 + i)*HS];
                p0 = fmaf(wd0[i], hv, p0);
                p1 = fmaf(wd1[i], hv, p1);
            }
            p0 += __shfl_xor_sync(0xffffffffu, p0, 1);
            p0 += __shfl_xor_sync(0xffffffffu, p0, 2);
            p0 += __shfl_xor_sync(0xffffffffu, p0, 4);
            p1 += __shfl_xor_sync(0xffffffffu, p1, 1);
            p1 += __shfl_xor_sync(0xffffffffu, p1, 2);
            p1 += __shfl_xor_sync(0xffffffffu, p1, 4);
            if (dsub == 0) {
                float L0 = p0 + bd0, L1 = p1 + bd1;
                float m = fmaxf(L0, L1);
                float lse = m + logf(expf(L0 - m) + expf(L1 - m));
                int bit = (s1 > 0.5f) ? 1 : 0;
                lp += (bit ? L1 : L0) - lse;
                sBit[drow] = bit;
            }
        }
        __syncthreads();   // sBit (and sH1 reads) settled for next step
    }

    if (dsub == 0) out[bidx] = lp;
}

extern "C" void kernel_launch(void* const* d_in, const int* in_sizes, int n_in,
                              void* d_out, int out_size) {
    (void)in_sizes; (void)n_in; (void)out_size;
    cudaFuncSetAttribute(rnn_wf_kernel,
                         cudaFuncAttributeMaxDynamicSharedMemorySize, SMEM_BYTES);
    rnn_wf_kernel<<<BATCH / BC, NTHREADS, SMEM_BYTES>>>(
        (const float*)d_in[0],
        (const float*)d_in[1], (const float*)d_in[2],
        (const float*)d_in[3], (const float*)d_in[4],
        (const float*)d_in[5], (const float*)d_in[6],
        (const float*)d_in[7], (const float*)d_in[8],
        (const float*)d_in[9], (const float*)d_in[10],
        (float*)d_out);
}

// round 4
// speedup vs baseline: 3.8153x; 3.8153x over previous
#include <cuda_runtime.h>
#include <cstdint>

#define NSTEP 128
#define BATCH 8192
#define BC    64
#define NT    256
#define HLD   260          // hcat row stride (words): (4g+t) mod 32 distinct -> conflict-free
#define WLD   132          // whh1 smem row stride (words)

// SMEM byte offsets
#define HCAT_OFF  0                         // 64 x 260 words (h0 | h1 | pad), tf32 bits
#define WHH1_OFF  (HCAT_OFF + 64*HLD*4)     // 128 x 132 words, tf32 bits
#define SPART_OFF (WHH1_OFF + 128*WLD*4)    // 8 warps x 2 x 64 floats
#define SBIT_OFF  (SPART_OFF + 8*128*4)     // 64 ints
#define SMEM_BYTES (SBIT_OFF + 64*4)

__device__ __forceinline__ uint32_t f2tf(float f) {
    uint32_t u; asm("cvt.rna.tf32.f32 %0, %1;" : "=r"(u) : "f"(f)); return u;
}
__device__ __forceinline__ float tanh_fast(float x) {
    float y; asm("tanh.approx.f32 %0, %1;" : "=f"(y) : "f"(x)); return y;
}
__device__ __forceinline__ void mma8(float* d, const uint32_t* a, const uint32_t* b) {
    asm volatile("mma.sync.aligned.m16n8k8.row.col.f32.tf32.tf32.f32 "
                 "{%0,%1,%2,%3}, {%4,%5,%6,%7}, {%8,%9}, {%0,%1,%2,%3};"
                 : "+f"(d[0]), "+f"(d[1]), "+f"(d[2]), "+f"(d[3])
                 : "r"(a[0]), "r"(a[1]), "r"(a[2]), "r"(a[3]), "r"(b[0]), "r"(b[1]));
}

__global__ void __launch_bounds__(NT, 1)
rnn_mma_kernel(const float* __restrict__ samples,
               const float* __restrict__ W_ih0, const float* __restrict__ b_ih0,
               const float* __restrict__ W_hh0, const float* __restrict__ b_hh0,
               const float* __restrict__ W_ih1, const float* __restrict__ b_ih1,
               const float* __restrict__ W_hh1, const float* __restrict__ b_hh1,
               const float* __restrict__ W_dense, const float* __restrict__ b_dense,
               float* __restrict__ out)
{
    extern __shared__ char smem[];
    uint32_t* hcat  = (uint32_t*)(smem + HCAT_OFF);
    uint32_t* whh1s = (uint32_t*)(smem + WHH1_OFF);
    float*    sPart = (float*)(smem + SPART_OFF);
    int*      sBit  = (int*)(smem + SBIT_OFF);

    const int tid = threadIdx.x;
    const int w   = tid >> 5;
    const int lane = tid & 31;
    const int g = lane >> 2;        // groupID (0..7)
    const int tq = lane & 3;        // threadID_in_group (0..3)
    const int jb = 16 * w + 2 * tq; // epilogue col base (D-frag cols 2t,2t+1)
    const int gRow = blockIdx.x * BC + tid;  // valid for tid<64

    // ---- resident weight fragments (tf32) ----
    uint32_t w0[2][16][2], wi1[2][16][2];
#pragma unroll
    for (int nt = 0; nt < 2; ++nt) {
        const int j = 16 * w + nt * 8 + g;
#pragma unroll
        for (int kt = 0; kt < 16; ++kt) {
            w0 [nt][kt][0] = f2tf(W_hh0[j * 128 + kt * 8 + tq]);
            w0 [nt][kt][1] = f2tf(W_hh0[j * 128 + kt * 8 + tq + 4]);
            wi1[nt][kt][0] = f2tf(W_ih1[j * 128 + kt * 8 + tq]);
            wi1[nt][kt][1] = f2tf(W_ih1[j * 128 + kt * 8 + tq + 4]);
        }
    }

    // ---- per-lane bias / select / dense tables (its 4 output cols) ----
    float cs0[4], cs1[4], cs2[4], b1r[4], wd0r[4], wd1r[4];
#pragma unroll
    for (int nt = 0; nt < 2; ++nt)
#pragma unroll
        for (int c = 0; c < 2; ++c) {
            const int jc = 16 * w + nt * 8 + 2 * tq + c;
            const int s = nt * 2 + c;
            float bb = b_ih0[jc] + b_hh0[jc];
            cs2[s] = bb;
            cs0[s] = bb + W_ih0[2 * jc];
            cs1[s] = bb + W_ih0[2 * jc + 1];
            b1r[s] = b_ih1[jc] + b_hh1[jc];
            wd0r[s] = W_dense[jc];
            wd1r[s] = W_dense[128 + jc];
        }
    const float bd0 = b_dense[0], bd1 = b_dense[1];

    // ---- SMEM init: W_hh1 (tf32), hcat zero, bits ----
    for (int idx = tid; idx < 128 * 128; idx += NT) {
        int j = idx >> 7, k = idx & 127;
        whh1s[j * WLD + k] = f2tf(W_hh1[idx]);
    }
    for (int idx = tid; idx < 64 * HLD; idx += NT) hcat[idx] = 0u;
    if (tid < 64) sBit[tid] = 2;
    __syncthreads();

    float lp = 0.f;

    for (int t = 0; t < NSTEP; ++t) {
        float s1 = 0.f;
        if (tid < 64) s1 = __ldg(&samples[(t * BATCH + gRow) * 2 + 1]);

        // ================= layer0: D = h0 @ W_hh0^T =================
        float acc[4][2][4];
#pragma unroll
        for (int mt = 0; mt < 4; ++mt)
#pragma unroll
            for (int nt = 0; nt < 2; ++nt)
#pragma unroll
                for (int i = 0; i < 4; ++i) acc[mt][nt][i] = 0.f;

#pragma unroll
        for (int kt = 0; kt < 16; ++kt) {
            uint32_t a[4][4];
#pragma unroll
            for (int mt = 0; mt < 4; ++mt) {
                const uint32_t* hb = hcat + (mt * 16 + g) * HLD + kt * 8 + tq;
                a[mt][0] = hb[0];
                a[mt][1] = hb[8 * HLD];
                a[mt][2] = hb[4];
                a[mt][3] = hb[8 * HLD + 4];
            }
#pragma unroll
            for (int mt = 0; mt < 4; ++mt) {
                mma8(acc[mt][0], a[mt], w0[0][kt]);
                mma8(acc[mt][1], a[mt], w0[1][kt]);
            }
        }
        __syncthreads();   // all reads of old h0 done

        // ---- epilogue0: h0' = tanh(D + bias + onehot) -> hcat[:,0:128] ----
#pragma unroll
        for (int mt = 0; mt < 4; ++mt)
#pragma unroll
            for (int hh = 0; hh < 2; ++hh) {
                const int row = mt * 16 + g + hh * 8;
                const int bit = sBit[row];
#pragma unroll
                for (int nt = 0; nt < 2; ++nt) {
                    uint32_t u0 = 0, u1 = 0;
#pragma unroll
                    for (int c = 0; c < 2; ++c) {
                        const int s = nt * 2 + c;
                        float base = (bit == 0) ? cs0[s] : ((bit == 1) ? cs1[s] : cs2[s]);
                        float v = acc[mt][nt][hh * 2 + c] + base;
                        uint32_t u = f2tf(tanh_fast(v));
                        if (c == 0) u0 = u; else u1 = u;
                    }
                    *(uint64_t*)(hcat + row * HLD + jb + nt * 8) =
                        (uint64_t)u0 | ((uint64_t)u1 << 32);
                }
            }
        __syncthreads();   // h0' visible

        // ================= layer1: D = [h0'|h1] @ [W_ih1|W_hh1]^T (K=256) =====
#pragma unroll
        for (int mt = 0; mt < 4; ++mt)
#pragma unroll
            for (int nt = 0; nt < 2; ++nt)
#pragma unroll
                for (int i = 0; i < 4; ++i) acc[mt][nt][i] = 0.f;

#pragma unroll
        for (int kt = 0; kt < 32; ++kt) {
            uint32_t a[4][4];
#pragma unroll
            for (int mt = 0; mt < 4; ++mt) {
                const uint32_t* hb = hcat + (mt * 16 + g) * HLD + kt * 8 + tq;
                a[mt][0] = hb[0];
                a[mt][1] = hb[8 * HLD];
                a[mt][2] = hb[4];
                a[mt][3] = hb[8 * HLD + 4];
            }
            uint32_t b[2][2];
            if (kt < 16) {
                b[0][0] = wi1[0][kt][0]; b[0][1] = wi1[0][kt][1];
                b[1][0] = wi1[1][kt][0]; b[1][1] = wi1[1][kt][1];
            } else {
#pragma unroll
                for (int nt = 0; nt < 2; ++nt) {
                    const uint32_t* wb = whh1s + (16 * w + nt * 8 + g) * WLD + (kt - 16) * 8 + tq;
                    b[nt][0] = wb[0];
                    b[nt][1] = wb[4];
                }
            }
#pragma unroll
            for (int mt = 0; mt < 4; ++mt) {
                mma8(acc[mt][0], a[mt], b[0]);
                mma8(acc[mt][1], a[mt], b[1]);
            }
        }
        __syncthreads();   // all reads of old h1 done

        // ---- epilogue1: h1' = tanh(D + b1) -> hcat[:,128:256]; dense partials ----
#pragma unroll
        for (int mt = 0; mt < 4; ++mt)
#pragma unroll
            for (int hh = 0; hh < 2; ++hh) {
                const int row = mt * 16 + g + hh * 8;
                float q0 = 0.f, q1 = 0.f;
#pragma unroll
                for (int nt = 0; nt < 2; ++nt) {
                    uint32_t u0 = 0, u1 = 0;
#pragma unroll
                    for (int c = 0; c < 2; ++c) {
                        const int s = nt * 2 + c;
                        float v = acc[mt][nt][hh * 2 + c] + b1r[s];
                        float th = tanh_fast(v);
                        q0 = fmaf(th, wd0r[s], q0);
                        q1 = fmaf(th, wd1r[s], q1);
                        uint32_t u = f2tf(th);
                        if (c == 0) u0 = u; else u1 = u;
                    }
                    *(uint64_t*)(hcat + row * HLD + 128 + jb + nt * 8) =
                        (uint64_t)u0 | ((uint64_t)u1 << 32);
                }
                q0 += __shfl_xor_sync(0xffffffffu, q0, 1);
                q0 += __shfl_xor_sync(0xffffffffu, q0, 2);
                q1 += __shfl_xor_sync(0xffffffffu, q1, 1);
                q1 += __shfl_xor_sync(0xffffffffu, q1, 2);
                if (tq == 0) {
                    sPart[w * 128 + row]      = q0;
                    sPart[w * 128 + 64 + row] = q1;
                }
            }
        __syncthreads();

        // ---- dense log-softmax + accumulate; publish next bits ----
        if (tid < 64) {
            float L0 = bd0, L1 = bd1;
#pragma unroll
            for (int ww = 0; ww < 8; ++ww) {
                L0 += sPart[ww * 128 + tid];
                L1 += sPart[ww * 128 + 64 + tid];
            }
            float m = fmaxf(L0, L1);
            float lse = m + __logf(__expf(L0 - m) + __expf(L1 - m));
            int bit = (s1 > 0.5f) ? 1 : 0;
            lp += (bit ? L1 : L0) - lse;
            sBit[tid] = bit;
        }
        __syncthreads();
    }

    if (tid < 64) out[gRow] = lp;
}

extern "C" void kernel_launch(void* const* d_in, const int* in_sizes, int n_in,
                              void* d_out, int out_size) {
    (void)in_sizes; (void)n_in; (void)out_size;
    cudaFuncSetAttribute(rnn_mma_kernel,
                         cudaFuncAttributeMaxDynamicSharedMemorySize, SMEM_BYTES);
    rnn_mma_kernel<<<BATCH / BC, NT, SMEM_BYTES>>>(
        (const float*)d_in[0],
        (const float*)d_in[1], (const float*)d_in[2],
        (const float*)d_in[3], (const float*)d_in[4],
        (const float*)d_in[5], (const float*)d_in[6],
        (const float*)d_in[7], (const float*)d_in[8],
        (const float*)d_in[9], (const float*)d_in[10],
        (float*)d_out);
}

// round 5
// speedup vs baseline: 4.3858x; 1.1495x over previous
#include <cuda_runtime.h>
#include <cstdint>

#define NSTEP 128
#define BATCH 8192
#define BC    32
#define NT    256
#define HLD   132            // hcat row stride in 32-bit words (bf16x2), conflict-free
#define WLD   132            // wB1 row stride in words

// ---- SMEM byte offsets ----
#define HCAT_OFF  0                          // 32 rows x HLD words: [h0(64w) | h1(64w) | pad]
#define WB1_OFF   (HCAT_OFF + BC*HLD*4)      // 128 rows x WLD words: [W_ih1(64w) | W_hh1(64w)]
#define SCTAB_OFF (WB1_OFF + 128*WLD*4)      // 3*128 floats (layer0 bias + one-hot select)
#define SB1V_OFF  (SCTAB_OFF + 1536)         // 128 floats
#define SWD_OFF   (SB1V_OFF + 512)           // 2*128 floats
#define SBIT_OFF  (SWD_OFF + 1024)           // 32 ints
#define SPART_OFF (SBIT_OFF + 128)           // 8 warps x 2 x 32 floats
#define SMEM_BYTES (SPART_OFF + 8*64*4)      // ~89.7KB -> 2 CTAs/SM

__device__ __forceinline__ uint32_t pk_bf(float even, float odd) {
    uint32_t r; asm("cvt.rn.bf16x2.f32 %0, %1, %2;" : "=r"(r) : "f"(odd), "f"(even));
    return r;   // lo = even(k), hi = odd(k+1)
}
__device__ __forceinline__ float tanh_fast(float x) {
    float y; asm("tanh.approx.f32 %0, %1;" : "=f"(y) : "f"(x)); return y;
}
__device__ __forceinline__ uint32_t smem_u32(const void* p) {
    uint32_t a;
    asm("{ .reg .u64 t; cvta.to.shared.u64 t, %1; cvt.u32.u64 %0, t; }" : "=r"(a) : "l"(p));
    return a;
}
__device__ __forceinline__ void ldmA(uint32_t* a, uint32_t addr) {
    asm volatile("ldmatrix.sync.aligned.m8n8.x4.shared.b16 {%0,%1,%2,%3}, [%4];"
                 : "=r"(a[0]), "=r"(a[1]), "=r"(a[2]), "=r"(a[3]) : "r"(addr));
}
__device__ __forceinline__ void mma16(float* d, const uint32_t* a, const uint32_t* b) {
    asm volatile("mma.sync.aligned.m16n8k16.row.col.f32.bf16.bf16.f32 "
                 "{%0,%1,%2,%3}, {%4,%5,%6,%7}, {%8,%9}, {%0,%1,%2,%3};"
                 : "+f"(d[0]), "+f"(d[1]), "+f"(d[2]), "+f"(d[3])
                 : "r"(a[0]), "r"(a[1]), "r"(a[2]), "r"(a[3]), "r"(b[0]), "r"(b[1]));
}

__global__ void __launch_bounds__(NT, 2)
rnn_bf16_kernel(const float* __restrict__ samples,
                const float* __restrict__ W_ih0, const float* __restrict__ b_ih0,
                const float* __restrict__ W_hh0, const float* __restrict__ b_hh0,
                const float* __restrict__ W_ih1, const float* __restrict__ b_ih1,
                const float* __restrict__ W_hh1, const float* __restrict__ b_hh1,
                const float* __restrict__ W_dense, const float* __restrict__ b_dense,
                float* __restrict__ out)
{
    extern __shared__ char smem[];
    uint32_t* hcat  = (uint32_t*)(smem + HCAT_OFF);
    uint32_t* wB1   = (uint32_t*)(smem + WB1_OFF);
    float*    scTab = (float*)(smem + SCTAB_OFF);
    float*    sB1v  = (float*)(smem + SB1V_OFF);
    float*    sWd   = (float*)(smem + SWD_OFF);
    int*      sBit  = (int*)(smem + SBIT_OFF);
    float*    sPart = (float*)(smem + SPART_OFF);

    const int tid = threadIdx.x;
    const int w   = tid >> 5;
    const int lane = tid & 31;
    const int g  = lane >> 2;         // groupID
    const int tq = lane & 3;          // thread-in-group
    const int gRow = blockIdx.x * BC + tid;   // valid for tid < 32

    // ---- resident W_hh0 B-fragments (bf16) ----
    uint32_t w0[2][8][2];
#pragma unroll
    for (int nt = 0; nt < 2; ++nt) {
        const int j = 16 * w + nt * 8 + g;
#pragma unroll
        for (int kt = 0; kt < 8; ++kt) {
            const float* p = W_hh0 + j * 128 + kt * 16;
            w0[nt][kt][0] = pk_bf(p[2 * tq],     p[2 * tq + 1]);
            w0[nt][kt][1] = pk_bf(p[8 + 2 * tq], p[8 + 2 * tq + 1]);
        }
    }

    // ---- SMEM weight/bias tables ----
    for (int idx = tid; idx < 128 * 64; idx += NT) {
        const int j = idx >> 6, kw = idx & 63;
        wB1[j * WLD + kw]      = pk_bf(W_ih1[j * 128 + 2 * kw], W_ih1[j * 128 + 2 * kw + 1]);
        wB1[j * WLD + 64 + kw] = pk_bf(W_hh1[j * 128 + 2 * kw], W_hh1[j * 128 + 2 * kw + 1]);
    }
    if (tid < 128) {
        const int j = tid;
        float bb = b_ih0[j] + b_hh0[j];
        scTab[j]       = bb + W_ih0[2 * j];
        scTab[128 + j] = bb + W_ih0[2 * j + 1];
        scTab[256 + j] = bb;
        sB1v[j] = b_ih1[j] + b_hh1[j];
        sWd[j]       = W_dense[j];
        sWd[128 + j] = W_dense[128 + j];
    }
    for (int idx = tid; idx < BC * HLD; idx += NT) hcat[idx] = 0u;
    if (tid < BC) sBit[tid] = 2;
    __syncthreads();

    // ldmatrix per-lane A address base
    const uint32_t hb = smem_u32(hcat)
        + (uint32_t)(((lane & 7) + ((lane >> 3) & 1) * 8) * HLD) * 4u
        + (uint32_t)(((lane >> 4) & 1) * 16);
    const float bd0 = b_dense[0], bd1 = b_dense[1];
    float lp = 0.f;

    for (int t = 0; t < NSTEP; ++t) {
        float s1 = 0.f;
        if (tid < BC) s1 = __ldg(&samples[(t * BATCH + gRow) * 2 + 1]);

        float acc[2][2][4];
#pragma unroll
        for (int mt = 0; mt < 2; ++mt)
#pragma unroll
            for (int nt = 0; nt < 2; ++nt)
#pragma unroll
                for (int i = 0; i < 4; ++i) acc[mt][nt][i] = 0.f;

        // ========== layer0: D = h0 @ W_hh0^T (K=128) ==========
#pragma unroll
        for (int kt = 0; kt < 8; ++kt) {
#pragma unroll
            for (int mt = 0; mt < 2; ++mt) {
                uint32_t a[4];
                ldmA(a, hb + (uint32_t)(mt * 16 * HLD * 4) + (uint32_t)(kt * 32));
                mma16(acc[mt][0], a, w0[0][kt]);
                mma16(acc[mt][1], a, w0[1][kt]);
            }
        }
        __syncthreads();   // reads of old h0 done

        // ---- epilogue0: h0' = tanh(D + bias + onehot) -> hcat words [0,64) ----
#pragma unroll
        for (int mt = 0; mt < 2; ++mt)
#pragma unroll
            for (int hh = 0; hh < 2; ++hh) {
                const int row = mt * 16 + g + hh * 8;
                const int bit = sBit[row];
                const float* cs = scTab + bit * 128;
#pragma unroll
                for (int nt = 0; nt < 2; ++nt) {
                    const int jc = 16 * w + nt * 8 + 2 * tq;
                    float v0 = acc[mt][nt][hh * 2]     + cs[jc];
                    float v1 = acc[mt][nt][hh * 2 + 1] + cs[jc + 1];
                    hcat[row * HLD + 8 * w + nt * 4 + tq] =
                        pk_bf(tanh_fast(v0), tanh_fast(v1));
                }
            }
        __syncthreads();   // h0' visible

        // ========== layer1: D = [h0'|h1] @ [W_ih1|W_hh1]^T (K=256) ==========
#pragma unroll
        for (int mt = 0; mt < 2; ++mt)
#pragma unroll
            for (int nt = 0; nt < 2; ++nt)
#pragma unroll
                for (int i = 0; i < 4; ++i) acc[mt][nt][i] = 0.f;

#pragma unroll
        for (int kt = 0; kt < 16; ++kt) {
            uint32_t b[2][2];
#pragma unroll
            for (int nt = 0; nt < 2; ++nt) {
                const uint32_t* wp = wB1 + (16 * w + nt * 8 + g) * WLD + kt * 8 + tq;
                b[nt][0] = wp[0];
                b[nt][1] = wp[4];
            }
#pragma unroll
            for (int mt = 0; mt < 2; ++mt) {
                uint32_t a[4];
                ldmA(a, hb + (uint32_t)(mt * 16 * HLD * 4) + (uint32_t)(kt * 32));
                mma16(acc[mt][0], a, b[0]);
                mma16(acc[mt][1], a, b[1]);
            }
        }
        __syncthreads();   // reads of old h1 done

        // ---- epilogue1: h1' = tanh(D + b1) -> words [64,128); dense partials ----
#pragma unroll
        for (int mt = 0; mt < 2; ++mt)
#pragma unroll
            for (int hh = 0; hh < 2; ++hh) {
                const int row = mt * 16 + g + hh * 8;
                float q0 = 0.f, q1 = 0.f;
#pragma unroll
                for (int nt = 0; nt < 2; ++nt) {
                    const int jc = 16 * w + nt * 8 + 2 * tq;
                    float v0 = acc[mt][nt][hh * 2]     + sB1v[jc];
                    float v1 = acc[mt][nt][hh * 2 + 1] + sB1v[jc + 1];
                    float t0 = tanh_fast(v0), t1 = tanh_fast(v1);
                    q0 = fmaf(t0, sWd[jc], fmaf(t1, sWd[jc + 1], q0));
                    q1 = fmaf(t0, sWd[128 + jc], fmaf(t1, sWd[128 + jc + 1], q1));
                    hcat[row * HLD + 64 + 8 * w + nt * 4 + tq] = pk_bf(t0, t1);
                }
                q0 += __shfl_xor_sync(0xffffffffu, q0, 1);
                q0 += __shfl_xor_sync(0xffffffffu, q0, 2);
                q1 += __shfl_xor_sync(0xffffffffu, q1, 1);
                q1 += __shfl_xor_sync(0xffffffffu, q1, 2);
                if (tq == 0) {
                    sPart[w * 64 + row]      = q0;
                    sPart[w * 64 + 32 + row] = q1;
                }
            }
        __syncthreads();

        // ---- dense log-softmax + accumulate; publish next-step bits ----
        if (tid < BC) {
            float L0 = bd0, L1 = bd1;
#pragma unroll
            for (int ww = 0; ww < 8; ++ww) {
                L0 += sPart[ww * 64 + tid];
                L1 += sPart[ww * 64 + 32 + tid];
            }
            float m = fmaxf(L0, L1);
            float lse = m + __logf(__expf(L0 - m) + __expf(L1 - m));
            int bit = (s1 > 0.5f) ? 1 : 0;
            lp += (bit ? L1 : L0) - lse;
            sBit[tid] = bit;
        }
        __syncthreads();
    }

    if (tid < BC) out[gRow] = lp;
}

extern "C" void kernel_launch(void* const* d_in, const int* in_sizes, int n_in,
                              void* d_out, int out_size) {
    (void)in_sizes; (void)n_in; (void)out_size;
    cudaFuncSetAttribute(rnn_bf16_kernel,
                         cudaFuncAttributeMaxDynamicSharedMemorySize, SMEM_BYTES);
    rnn_bf16_kernel<<<BATCH / BC, NT, SMEM_BYTES>>>(
        (const float*)d_in[0],
        (const float*)d_in[1], (const float*)d_in[2],
        (const float*)d_in[3], (const float*)d_in[4],
        (const float*)d_in[5], (const float*)d_in[6],
        (const float*)d_in[7], (const float*)d_in[8],
        (const float*)d_in[9], (const float*)d_in[10],
        (float*)d_out);
}

// round 6
// speedup vs baseline: 6.9793x; 1.5914x over previous
#include <cuda_runtime.h>
#include <cstdint>

#define NSTEP 128
#define BATCH 8192
#define BC    32
#define NT    256
#define HLD   132            // hcat row stride in 32-bit words (bf16x2), conflict-free
#define WLD   132            // wB1 row stride in words
#define HBUF  (BC*HLD)       // one hcat buffer, words

// ---- SMEM byte offsets ----
#define HCAT_OFF  0                          // 2 buffers x 32 rows x HLD words: [h0|h1|pad]
#define WB1_OFF   (HCAT_OFF + 2*HBUF*4)      // 128 rows x WLD words: [W_ih1(64w) | W_hh1(64w)]
#define SCTAB_OFF (WB1_OFF + 128*WLD*4)      // 3*128 floats (layer0 bias + one-hot select)
#define SB1V_OFF  (SCTAB_OFF + 1536)         // 128 floats
#define SWD_OFF   (SB1V_OFF + 512)           // 2*128 floats
#define SBIT_OFF  (SWD_OFF + 1024)           // 32 ints
#define SPART_OFF (SBIT_OFF + 128)           // 8 warps x 2 x 32 floats
#define SMEM_BYTES (SPART_OFF + 8*64*4)      // ~107KB -> 2 CTAs/SM

__device__ __forceinline__ uint32_t pk_bf(float even, float odd) {
    uint32_t r; asm("cvt.rn.bf16x2.f32 %0, %1, %2;" : "=r"(r) : "f"(odd), "f"(even));
    return r;
}
__device__ __forceinline__ float tanh_fast(float x) {
    float y; asm("tanh.approx.f32 %0, %1;" : "=f"(y) : "f"(x)); return y;
}
__device__ __forceinline__ uint32_t smem_u32(const void* p) {
    uint32_t a;
    asm("{ .reg .u64 t; cvta.to.shared.u64 t, %1; cvt.u32.u64 %0, t; }" : "=r"(a) : "l"(p));
    return a;
}
__device__ __forceinline__ void ldmA(uint32_t* a, uint32_t addr) {
    asm volatile("ldmatrix.sync.aligned.m8n8.x4.shared.b16 {%0,%1,%2,%3}, [%4];"
                 : "=r"(a[0]), "=r"(a[1]), "=r"(a[2]), "=r"(a[3]) : "r"(addr));
}
__device__ __forceinline__ void mma16(float* d, const uint32_t* a, const uint32_t* b) {
    asm volatile("mma.sync.aligned.m16n8k16.row.col.f32.bf16.bf16.f32 "
                 "{%0,%1,%2,%3}, {%4,%5,%6,%7}, {%8,%9}, {%0,%1,%2,%3};"
                 : "+f"(d[0]), "+f"(d[1]), "+f"(d[2]), "+f"(d[3])
                 : "r"(a[0]), "r"(a[1]), "r"(a[2]), "r"(a[3]), "r"(b[0]), "r"(b[1]));
}
#define BAR_SYNC(id)   asm volatile("bar.sync %0, %1;"   :: "n"(id), "n"(NT) : "memory")
#define BAR_ARRIVE(id) asm volatile("bar.arrive %0, %1;" :: "n"(id), "n"(NT) : "memory")

__global__ void __launch_bounds__(NT, 2)
rnn_bf16p_kernel(const float* __restrict__ samples,
                 const float* __restrict__ W_ih0, const float* __restrict__ b_ih0,
                 const float* __restrict__ W_hh0, const float* __restrict__ b_hh0,
                 const float* __restrict__ W_ih1, const float* __restrict__ b_ih1,
                 const float* __restrict__ W_hh1, const float* __restrict__ b_hh1,
                 const float* __restrict__ W_dense, const float* __restrict__ b_dense,
                 float* __restrict__ out)
{
    extern __shared__ char smem[];
    uint32_t* hcat  = (uint32_t*)(smem + HCAT_OFF);
    uint32_t* wB1   = (uint32_t*)(smem + WB1_OFF);
    float*    scTab = (float*)(smem + SCTAB_OFF);
    float*    sB1v  = (float*)(smem + SB1V_OFF);
    float*    sWd   = (float*)(smem + SWD_OFF);
    int*      sBit  = (int*)(smem + SBIT_OFF);
    float*    sPart = (float*)(smem + SPART_OFF);

    const int tid = threadIdx.x;
    const int w   = tid >> 5;
    const int lane = tid & 31;
    const int g  = lane >> 2;
    const int tq = lane & 3;
    const int gRow = blockIdx.x * BC + tid;   // valid for tid < 32

    // ---- resident W_hh0 B-fragments (bf16) ----
    uint32_t w0[2][8][2];
#pragma unroll
    for (int nt = 0; nt < 2; ++nt) {
        const int j = 16 * w + nt * 8 + g;
#pragma unroll
        for (int kt = 0; kt < 8; ++kt) {
            const float* p = W_hh0 + j * 128 + kt * 16;
            w0[nt][kt][0] = pk_bf(p[2 * tq],     p[2 * tq + 1]);
            w0[nt][kt][1] = pk_bf(p[8 + 2 * tq], p[8 + 2 * tq + 1]);
        }
    }

    // ---- SMEM weight/bias tables ----
    for (int idx = tid; idx < 128 * 64; idx += NT) {
        const int j = idx >> 6, kw = idx & 63;
        wB1[j * WLD + kw]      = pk_bf(W_ih1[j * 128 + 2 * kw], W_ih1[j * 128 + 2 * kw + 1]);
        wB1[j * WLD + 64 + kw] = pk_bf(W_hh1[j * 128 + 2 * kw], W_hh1[j * 128 + 2 * kw + 1]);
    }
    if (tid < 128) {
        const int j = tid;
        float bb = b_ih0[j] + b_hh0[j];
        scTab[j]       = bb + W_ih0[2 * j];
        scTab[128 + j] = bb + W_ih0[2 * j + 1];
        scTab[256 + j] = bb;
        sB1v[j] = b_ih1[j] + b_hh1[j];
        sWd[j]       = W_dense[j];
        sWd[128 + j] = W_dense[128 + j];
    }
    for (int idx = tid; idx < HBUF; idx += NT) hcat[idx] = 0u;   // buffer 0 zeroed
    if (tid < BC) sBit[tid] = 2;
    __syncthreads();

    // ldmatrix per-lane A address base (buffer 0)
    const uint32_t hb0 = smem_u32(hcat)
        + (uint32_t)(((lane & 7) + ((lane >> 3) & 1) * 8) * HLD) * 4u
        + (uint32_t)(((lane >> 4) & 1) * 16);
    const float bd0 = b_dense[0], bd1 = b_dense[1];
    float lp = 0.f;

    for (int t = 0; t < NSTEP; ++t) {
        const uint32_t rdoff = (uint32_t)(t & 1) * (HBUF * 4);
        const uint32_t wroff = (uint32_t)((t & 1) ^ 1) * (HBUF * 4);
        const uint32_t* hcw = hcat + ((t & 1) ^ 1) * HBUF;  // write buffer (word ptr)
        uint32_t* hcwm = (uint32_t*)hcw;

        float s1 = 0.f;
        if (tid < BC) s1 = __ldg(&samples[(t * BATCH + gRow) * 2 + 1]);

        // ========== layer0: D = h0[rd] @ W_hh0^T (K=128) ==========
        float acc[2][2][4];
#pragma unroll
        for (int mt = 0; mt < 2; ++mt)
#pragma unroll
            for (int nt = 0; nt < 2; ++nt)
#pragma unroll
                for (int i = 0; i < 4; ++i) acc[mt][nt][i] = 0.f;

#pragma unroll
        for (int kt = 0; kt < 8; ++kt) {
#pragma unroll
            for (int mt = 0; mt < 2; ++mt) {
                uint32_t a[4];
                ldmA(a, hb0 + rdoff + (uint32_t)(mt * 16 * HLD * 4) + (uint32_t)(kt * 32));
                mma16(acc[mt][0], a, w0[0][kt]);
                mma16(acc[mt][1], a, w0[1][kt]);
            }
        }

        // join point: warp0's dense(t-1) sBit writes become visible here
        BAR_SYNC(1);

        // ---- epilogue0: h0' = tanh(D + bias + onehot) -> h0[wr] ----
#pragma unroll
        for (int mt = 0; mt < 2; ++mt)
#pragma unroll
            for (int hh = 0; hh < 2; ++hh) {
                const int row = mt * 16 + g + hh * 8;
                const int bit = sBit[row];
                const float* cs = scTab + bit * 128;
#pragma unroll
                for (int nt = 0; nt < 2; ++nt) {
                    const int jc = 16 * w + nt * 8 + 2 * tq;
                    float v0 = acc[mt][nt][hh * 2]     + cs[jc];
                    float v1 = acc[mt][nt][hh * 2 + 1] + cs[jc + 1];
                    hcwm[row * HLD + 8 * w + nt * 4 + tq] =
                        pk_bf(tanh_fast(v0), tanh_fast(v1));
                }
            }
        __syncthreads();   // h0'[wr] visible to all warps

        // ========== layer1: D = [h0'[wr] | h1[rd]] @ [W_ih1|W_hh1]^T (K=256) ==========
#pragma unroll
        for (int mt = 0; mt < 2; ++mt)
#pragma unroll
            for (int nt = 0; nt < 2; ++nt)
#pragma unroll
                for (int i = 0; i < 4; ++i) acc[mt][nt][i] = 0.f;

#pragma unroll
        for (int kt = 0; kt < 16; ++kt) {
            uint32_t b[2][2];
#pragma unroll
            for (int nt = 0; nt < 2; ++nt) {
                const uint32_t* wp = wB1 + (16 * w + nt * 8 + g) * WLD + kt * 8 + tq;
                b[nt][0] = wp[0];
                b[nt][1] = wp[4];
            }
            const uint32_t abase = (kt < 8)
                ? (hb0 + wroff + (uint32_t)(kt * 32))                 // h0' in write buf
                : (hb0 + rdoff + 256u + (uint32_t)((kt - 8) * 32));   // h1 in read buf (+64 words)
#pragma unroll
            for (int mt = 0; mt < 2; ++mt) {
                uint32_t a[4];
                ldmA(a, abase + (uint32_t)(mt * 16 * HLD * 4));
                mma16(acc[mt][0], a, b[0]);
                mma16(acc[mt][1], a, b[1]);
            }
        }

        // ---- epilogue1: h1' = tanh(D + b1) -> h1[wr]; dense partials ----
#pragma unroll
        for (int mt = 0; mt < 2; ++mt)
#pragma unroll
            for (int hh = 0; hh < 2; ++hh) {
                const int row = mt * 16 + g + hh * 8;
                float q0 = 0.f, q1 = 0.f;
#pragma unroll
                for (int nt = 0; nt < 2; ++nt) {
                    const int jc = 16 * w + nt * 8 + 2 * tq;
                    float v0 = acc[mt][nt][hh * 2]     + sB1v[jc];
                    float v1 = acc[mt][nt][hh * 2 + 1] + sB1v[jc + 1];
                    float t0 = tanh_fast(v0), t1 = tanh_fast(v1);
                    q0 = fmaf(t0, sWd[jc], fmaf(t1, sWd[jc + 1], q0));
                    q1 = fmaf(t0, sWd[128 + jc], fmaf(t1, sWd[128 + jc + 1], q1));
                    hcwm[row * HLD + 64 + 8 * w + nt * 4 + tq] = pk_bf(t0, t1);
                }
                q0 += __shfl_xor_sync(0xffffffffu, q0, 1);
                q0 += __shfl_xor_sync(0xffffffffu, q0, 2);
                q1 += __shfl_xor_sync(0xffffffffu, q1, 1);
                q1 += __shfl_xor_sync(0xffffffffu, q1, 2);
                if (tq == 0) {
                    sPart[w * 64 + row]      = q0;
                    sPart[w * 64 + 32 + row] = q1;
                }
            }

        // ---- dense tail: only warp 0 blocks; warps 1-7 run ahead into l0(t+1) ----
        if (w == 0) {
            BAR_SYNC(2);        // wait for all sPart writes
            float L0 = bd0, L1 = bd1;
#pragma unroll
            for (int ww = 0; ww < 8; ++ww) {
                L0 += sPart[ww * 64 + lane];
                L1 += sPart[ww * 64 + 32 + lane];
            }
            float m = fmaxf(L0, L1);
            float lse = m + __logf(__expf(L0 - m) + __expf(L1 - m));
            int bit = (s1 > 0.5f) ? 1 : 0;
            lp += (bit ? L1 : L0) - lse;
            sBit[lane] = bit;
        } else {
            BAR_ARRIVE(2);
        }
    }

    if (tid < BC) out[gRow] = lp;
}

extern "C" void kernel_launch(void* const* d_in, const int* in_sizes, int n_in,
                              void* d_out, int out_size) {
    (void)in_sizes; (void)n_in; (void)out_size;
    cudaFuncSetAttribute(rnn_bf16p_kernel,
                         cudaFuncAttributeMaxDynamicSharedMemorySize, SMEM_BYTES);
    rnn_bf16p_kernel<<<BATCH / BC, NT, SMEM_BYTES>>>(
        (const float*)d_in[0],
        (const float*)d_in[1], (const float*)d_in[2],
        (const float*)d_in[3], (const float*)d_in[4],
        (const float*)d_in[5], (const float*)d_in[6],
        (const float*)d_in[7], (const float*)d_in[8],
        (const float*)d_in[9], (const float*)d_in[10],
        (float*)d_out);
}

// round 7
// speedup vs baseline: 8.6590x; 1.2407x over previous
#include <cuda_runtime.h>
#include <cstdint>

#define NSTEP 128
#define BATCH 8192
#define BC    32
#define NT    128
#define HLD   132            // hcat row stride in 32-bit words (bf16x2), conflict-free
#define WLD   132            // wB1 row stride in words
#define HBUF  (BC*HLD)       // one hcat buffer, words

// ---- SMEM byte offsets ----
#define HCAT_OFF  0                          // 2 buffers x 32 rows x HLD words: [h0|h1|pad]
#define WB1_OFF   (HCAT_OFF + 2*HBUF*4)      // 128 rows x WLD words: [W_ih1(64w) | W_hh1(64w)]
#define SCTAB_OFF (WB1_OFF + 128*WLD*4)      // 3*128 floats (layer0 bias + one-hot select)
#define SB1V_OFF  (SCTAB_OFF + 1536)         // 128 floats
#define SWD_OFF   (SB1V_OFF + 512)           // 2*128 floats
#define SBIT_OFF  (SWD_OFF + 1024)           // 32 ints
#define SPART_OFF (SBIT_OFF + 128)           // 4 warps x 2 x 32 floats
#define SMEM_BYTES (SPART_OFF + 4*64*4)      // ~107KB -> 2 CTAs/SM

__device__ __forceinline__ uint32_t pk_bf(float even, float odd) {
    uint32_t r; asm("cvt.rn.bf16x2.f32 %0, %1, %2;" : "=r"(r) : "f"(odd), "f"(even));
    return r;
}
__device__ __forceinline__ float tanh_fast(float x) {
    float y; asm("tanh.approx.f32 %0, %1;" : "=f"(y) : "f"(x)); return y;
}
__device__ __forceinline__ uint32_t smem_u32(const void* p) {
    uint32_t a;
    asm("{ .reg .u64 t; cvta.to.shared.u64 t, %1; cvt.u32.u64 %0, t; }" : "=r"(a) : "l"(p));
    return a;
}
__device__ __forceinline__ void ldmA(uint32_t* a, uint32_t addr) {
    asm volatile("ldmatrix.sync.aligned.m8n8.x4.shared.b16 {%0,%1,%2,%3}, [%4];"
                 : "=r"(a[0]), "=r"(a[1]), "=r"(a[2]), "=r"(a[3]) : "r"(addr));
}
__device__ __forceinline__ void mma16(float* d, const uint32_t* a, const uint32_t* b) {
    asm volatile("mma.sync.aligned.m16n8k16.row.col.f32.bf16.bf16.f32 "
                 "{%0,%1,%2,%3}, {%4,%5,%6,%7}, {%8,%9}, {%0,%1,%2,%3};"
                 : "+f"(d[0]), "+f"(d[1]), "+f"(d[2]), "+f"(d[3])
                 : "r"(a[0]), "r"(a[1]), "r"(a[2]), "r"(a[3]), "r"(b[0]), "r"(b[1]));
}
#define BAR_SYNC(id)   asm volatile("bar.sync %0, %1;"   :: "n"(id), "n"(NT) : "memory")
#define BAR_ARRIVE(id) asm volatile("bar.arrive %0, %1;" :: "n"(id), "n"(NT) : "memory")

__global__ void __launch_bounds__(NT, 2)
rnn_bf16w_kernel(const float* __restrict__ samples,
                 const float* __restrict__ W_ih0, const float* __restrict__ b_ih0,
                 const float* __restrict__ W_hh0, const float* __restrict__ b_hh0,
                 const float* __restrict__ W_ih1, const float* __restrict__ b_ih1,
                 const float* __restrict__ W_hh1, const float* __restrict__ b_hh1,
                 const float* __restrict__ W_dense, const float* __restrict__ b_dense,
                 float* __restrict__ out)
{
    extern __shared__ char smem[];
    uint32_t* hcat  = (uint32_t*)(smem + HCAT_OFF);
    uint32_t* wB1   = (uint32_t*)(smem + WB1_OFF);
    float*    scTab = (float*)(smem + SCTAB_OFF);
    float*    sB1v  = (float*)(smem + SB1V_OFF);
    float*    sWd   = (float*)(smem + SWD_OFF);
    int*      sBit  = (int*)(smem + SBIT_OFF);
    float*    sPart = (float*)(smem + SPART_OFF);

    const int tid = threadIdx.x;
    const int w   = tid >> 5;         // 0..3, owns 32 n-cols
    const int lane = tid & 31;
    const int g  = lane >> 2;
    const int tq = lane & 3;
    const int gRow = blockIdx.x * BC + tid;   // valid for tid < 32

    // ---- resident W_hh0 B-fragments (bf16): 4 n8-tiles x 8 k-tiles ----
    uint32_t w0[4][8][2];
#pragma unroll
    for (int nt = 0; nt < 4; ++nt) {
        const int j = 32 * w + nt * 8 + g;
#pragma unroll
        for (int kt = 0; kt < 8; ++kt) {
            const float* p = W_hh0 + j * 128 + kt * 16;
            w0[nt][kt][0] = pk_bf(p[2 * tq],     p[2 * tq + 1]);
            w0[nt][kt][1] = pk_bf(p[8 + 2 * tq], p[8 + 2 * tq + 1]);
        }
    }

    // ---- SMEM weight/bias tables ----
    for (int idx = tid; idx < 128 * 64; idx += NT) {
        const int j = idx >> 6, kw = idx & 63;
        wB1[j * WLD + kw]      = pk_bf(W_ih1[j * 128 + 2 * kw], W_ih1[j * 128 + 2 * kw + 1]);
        wB1[j * WLD + 64 + kw] = pk_bf(W_hh1[j * 128 + 2 * kw], W_hh1[j * 128 + 2 * kw + 1]);
    }
    if (tid < 128) {
        const int j = tid;
        float bb = b_ih0[j] + b_hh0[j];
        scTab[j]       = bb + W_ih0[2 * j];
        scTab[128 + j] = bb + W_ih0[2 * j + 1];
        scTab[256 + j] = bb;
        sB1v[j] = b_ih1[j] + b_hh1[j];
        sWd[j]       = W_dense[j];
        sWd[128 + j] = W_dense[128 + j];
    }
    for (int idx = tid; idx < HBUF; idx += NT) hcat[idx] = 0u;   // buffer 0 zeroed
    if (tid < BC) sBit[tid] = 2;
    __syncthreads();

    // ldmatrix per-lane A address base (buffer 0)
    const uint32_t hb0 = smem_u32(hcat)
        + (uint32_t)(((lane & 7) + ((lane >> 3) & 1) * 8) * HLD) * 4u
        + (uint32_t)(((lane >> 4) & 1) * 16);
    const float bd0 = b_dense[0], bd1 = b_dense[1];
    float lp = 0.f;

    for (int t = 0; t < NSTEP; ++t) {
        const uint32_t rdoff = (uint32_t)(t & 1) * (HBUF * 4);
        const uint32_t wroff = (uint32_t)((t & 1) ^ 1) * (HBUF * 4);
        uint32_t* hcwm = hcat + ((t & 1) ^ 1) * HBUF;   // write buffer

        float s1 = 0.f;
        if (tid < BC) s1 = __ldg(&samples[(t * BATCH + gRow) * 2 + 1]);

        // ========== layer0: D = h0[rd] @ W_hh0^T (K=128) ==========
        float acc[2][4][4];
#pragma unroll
        for (int mt = 0; mt < 2; ++mt)
#pragma unroll
            for (int nt = 0; nt < 4; ++nt)
#pragma unroll
                for (int i = 0; i < 4; ++i) acc[mt][nt][i] = 0.f;

#pragma unroll
        for (int kt = 0; kt < 8; ++kt) {
#pragma unroll
            for (int mt = 0; mt < 2; ++mt) {
                uint32_t a[4];
                ldmA(a, hb0 + rdoff + (uint32_t)(mt * 16 * HLD * 4) + (uint32_t)(kt * 32));
#pragma unroll
                for (int nt = 0; nt < 4; ++nt)
                    mma16(acc[mt][nt], a, w0[nt][kt]);
            }
        }

        // join point: warp0's dense(t-1) sBit writes become visible here
        BAR_SYNC(1);

        // ---- epilogue0: h0' = tanh(D + bias + onehot) -> h0[wr] ----
#pragma unroll
        for (int mt = 0; mt < 2; ++mt)
#pragma unroll
            for (int hh = 0; hh < 2; ++hh) {
                const int row = mt * 16 + g + hh * 8;
                const int bit = sBit[row];
                const float* cs = scTab + bit * 128;
#pragma unroll
                for (int nt = 0; nt < 4; ++nt) {
                    const int jc = 32 * w + nt * 8 + 2 * tq;
                    float v0 = acc[mt][nt][hh * 2]     + cs[jc];
                    float v1 = acc[mt][nt][hh * 2 + 1] + cs[jc + 1];
                    hcwm[row * HLD + 16 * w + nt * 4 + tq] =
                        pk_bf(tanh_fast(v0), tanh_fast(v1));
                }
            }
        __syncthreads();   // h0'[wr] visible to all warps

        // ========== layer1: D = [h0'[wr] | h1[rd]] @ [W_ih1|W_hh1]^T (K=256) ==========
#pragma unroll
        for (int mt = 0; mt < 2; ++mt)
#pragma unroll
            for (int nt = 0; nt < 4; ++nt)
#pragma unroll
                for (int i = 0; i < 4; ++i) acc[mt][nt][i] = 0.f;

#pragma unroll
        for (int kt = 0; kt < 16; ++kt) {
            uint32_t b[4][2];
#pragma unroll
            for (int nt = 0; nt < 4; ++nt) {
                const uint32_t* wp = wB1 + (32 * w + nt * 8 + g) * WLD + kt * 8 + tq;
                b[nt][0] = wp[0];
                b[nt][1] = wp[4];
            }
            const uint32_t abase = (kt < 8)
                ? (hb0 + wroff + (uint32_t)(kt * 32))                 // h0' in write buf
                : (hb0 + rdoff + 256u + (uint32_t)((kt - 8) * 32));   // h1 in read buf
#pragma unroll
            for (int mt = 0; mt < 2; ++mt) {
                uint32_t a[4];
                ldmA(a, abase + (uint32_t)(mt * 16 * HLD * 4));
#pragma unroll
                for (int nt = 0; nt < 4; ++nt)
                    mma16(acc[mt][nt], a, b[nt]);
            }
        }

        // ---- epilogue1: h1' = tanh(D + b1) -> h1[wr]; dense partials ----
#pragma unroll
        for (int mt = 0; mt < 2; ++mt)
#pragma unroll
            for (int hh = 0; hh < 2; ++hh) {
                const int row = mt * 16 + g + hh * 8;
                float q0 = 0.f, q1 = 0.f;
#pragma unroll
                for (int nt = 0; nt < 4; ++nt) {
                    const int jc = 32 * w + nt * 8 + 2 * tq;
                    float v0 = acc[mt][nt][hh * 2]     + sB1v[jc];
                    float v1 = acc[mt][nt][hh * 2 + 1] + sB1v[jc + 1];
                    float t0 = tanh_fast(v0), t1 = tanh_fast(v1);
                    q0 = fmaf(t0, sWd[jc], fmaf(t1, sWd[jc + 1], q0));
                    q1 = fmaf(t0, sWd[128 + jc], fmaf(t1, sWd[128 + jc + 1], q1));
                    hcwm[row * HLD + 64 + 16 * w + nt * 4 + tq] = pk_bf(t0, t1);
                }
                q0 += __shfl_xor_sync(0xffffffffu, q0, 1);
                q0 += __shfl_xor_sync(0xffffffffu, q0, 2);
                q1 += __shfl_xor_sync(0xffffffffu, q1, 1);
                q1 += __shfl_xor_sync(0xffffffffu, q1, 2);
                if (tq == 0) {
                    sPart[w * 64 + row]      = q0;
                    sPart[w * 64 + 32 + row] = q1;
                }
            }

        // ---- dense tail: only warp 0 blocks; warps 1-3 run ahead into l0(t+1) ----
        if (w == 0) {
            BAR_SYNC(2);        // wait for all sPart writes
            float L0 = bd0, L1 = bd1;
#pragma unroll
            for (int ww = 0; ww < 4; ++ww) {
                L0 += sPart[ww * 64 + lane];
                L1 += sPart[ww * 64 + 32 + lane];
            }
            float m = fmaxf(L0, L1);
            float lse = m + __logf(__expf(L0 - m) + __expf(L1 - m));
            int bit = (s1 > 0.5f) ? 1 : 0;
            lp += (bit ? L1 : L0) - lse;
            sBit[lane] = bit;
        } else {
            BAR_ARRIVE(2);
        }
    }

    if (tid < BC) out[gRow] = lp;
}

extern "C" void kernel_launch(void* const* d_in, const int* in_sizes, int n_in,
                              void* d_out, int out_size) {
    (void)in_sizes; (void)n_in; (void)out_size;
    cudaFuncSetAttribute(rnn_bf16w_kernel,
                         cudaFuncAttributeMaxDynamicSharedMemorySize, SMEM_BYTES);
    rnn_bf16w_kernel<<<BATCH / BC, NT, SMEM_BYTES>>>(
        (const float*)d_in[0],
        (const float*)d_in[1], (const float*)d_in[2],
        (const float*)d_in[3], (const float*)d_in[4],
        (const float*)d_in[5], (const float*)d_in[6],
        (const float*)d_in[7], (const float*)d_in[8],
        (const float*)d_in[9], (const float*)d_in[10],
        (float*)d_out);
}

// round 9
// speedup vs baseline: 8.6752x; 1.0019x over previous
#include <cuda_runtime.h>
#include <cstdint>

#define NSTEP 128
#define BATCH 8192
#define BC    32
#define NT    128
#define HLD   132            // hcat row stride in 32-bit words (bf16x2), conflict-free
#define WLD   132            // wB1 row stride in words
#define HBUF  (BC*HLD)       // one hcat buffer, words

// ---- SMEM byte offsets ----
#define HCAT_OFF  0                          // 2 buffers x 32 rows x HLD words: [h0|h1|pad]
#define WB1_OFF   (HCAT_OFF + 2*HBUF*4)      // 128 rows x WLD words: [W_ih1(64w) | W_hh1(64w)]
#define SCTAB_OFF (WB1_OFF + 128*WLD*4)      // 3*128 floats (layer0 bias + one-hot select)
#define SB1V_OFF  (SCTAB_OFF + 1536)         // 128 floats
#define SWD_OFF   (SB1V_OFF + 512)           // 2*128 floats
#define SBIT_OFF  (SWD_OFF + 1024)           // 32 ints
#define SPART_OFF (SBIT_OFF + 128)           // 4 warps x 2 x 32 floats
#define SMEM_BYTES (SPART_OFF + 4*64*4)      // ~107KB -> 2 CTAs/SM

__device__ __forceinline__ uint32_t pk_bf(float even, float odd) {
    uint32_t r; asm("cvt.rn.bf16x2.f32 %0, %1, %2;" : "=r"(r) : "f"(odd), "f"(even));
    return r;
}
__device__ __forceinline__ float tanh_fast(float x) {
    float y; asm("tanh.approx.f32 %0, %1;" : "=f"(y) : "f"(x)); return y;
}
__device__ __forceinline__ uint32_t smem_u32(const void* p) {
    uint32_t a;
    asm("{ .reg .u64 t; cvta.to.shared.u64 t, %1; cvt.u32.u64 %0, t; }" : "=r"(a) : "l"(p));
    return a;
}
__device__ __forceinline__ void ldmA(uint32_t* a, uint32_t addr) {
    asm volatile("ldmatrix.sync.aligned.m8n8.x4.shared.b16 {%0,%1,%2,%3}, [%4];"
                 : "=r"(a[0]), "=r"(a[1]), "=r"(a[2]), "=r"(a[3]) : "r"(addr));
}
__device__ __forceinline__ void mma16(float* d, const uint32_t* a, const uint32_t* b) {
    asm volatile("mma.sync.aligned.m16n8k16.row.col.f32.bf16.bf16.f32 "
                 "{%0,%1,%2,%3}, {%4,%5,%6,%7}, {%8,%9}, {%0,%1,%2,%3};"
                 : "+f"(d[0]), "+f"(d[1]), "+f"(d[2]), "+f"(d[3])
                 : "r"(a[0]), "r"(a[1]), "r"(a[2]), "r"(a[3]), "r"(b[0]), "r"(b[1]));
}
#define BAR_SYNC(id)   asm volatile("bar.sync %0, %1;"   :: "n"(id), "n"(NT) : "memory")
#define BAR_ARRIVE(id) asm volatile("bar.arrive %0, %1;" :: "n"(id), "n"(NT) : "memory")

__global__ void __launch_bounds__(NT, 2)
rnn_bf16s_kernel(const float* __restrict__ samples,
                 const float* __restrict__ W_ih0, const float* __restrict__ b_ih0,
                 const float* __restrict__ W_hh0, const float* __restrict__ b_hh0,
                 const float* __restrict__ W_ih1, const float* __restrict__ b_ih1,
                 const float* __restrict__ W_hh1, const float* __restrict__ b_hh1,
                 const float* __restrict__ W_dense, const float* __restrict__ b_dense,
                 float* __restrict__ out)
{
    extern __shared__ char smem[];
    uint32_t* hcat  = (uint32_t*)(smem + HCAT_OFF);
    uint32_t* wB1   = (uint32_t*)(smem + WB1_OFF);
    float*    scTab = (float*)(smem + SCTAB_OFF);
    float*    sB1v  = (float*)(smem + SB1V_OFF);
    float*    sWd   = (float*)(smem + SWD_OFF);
    int*      sBit  = (int*)(smem + SBIT_OFF);
    float*    sPart = (float*)(smem + SPART_OFF);

    const int tid = threadIdx.x;
    const int w   = tid >> 5;         // 0..3, owns 32 n-cols
    const int lane = tid & 31;
    const int g  = lane >> 2;
    const int tq = lane & 3;
    const int gRow = blockIdx.x * BC + tid;   // valid for tid < 32

    // ---- resident W_hh0 B-fragments (bf16): 4 n8-tiles x 8 k-tiles ----
    uint32_t w0[4][8][2];
#pragma unroll
    for (int nt = 0; nt < 4; ++nt) {
        const int j = 32 * w + nt * 8 + g;
#pragma unroll
        for (int kt = 0; kt < 8; ++kt) {
            const float* p = W_hh0 + j * 128 + kt * 16;
            w0[nt][kt][0] = pk_bf(p[2 * tq],     p[2 * tq + 1]);
            w0[nt][kt][1] = pk_bf(p[8 + 2 * tq], p[8 + 2 * tq + 1]);
        }
    }

    // ---- SMEM weight/bias tables ----
    for (int idx = tid; idx < 128 * 64; idx += NT) {
        const int j = idx >> 6, kw = idx & 63;
        wB1[j * WLD + kw]      = pk_bf(W_ih1[j * 128 + 2 * kw], W_ih1[j * 128 + 2 * kw + 1]);
        wB1[j * WLD + 64 + kw] = pk_bf(W_hh1[j * 128 + 2 * kw], W_hh1[j * 128 + 2 * kw + 1]);
    }
    if (tid < 128) {
        const int j = tid;
        float bb = b_ih0[j] + b_hh0[j];
        scTab[j]       = bb + W_ih0[2 * j];
        scTab[128 + j] = bb + W_ih0[2 * j + 1];
        scTab[256 + j] = bb;
        sB1v[j] = b_ih1[j] + b_hh1[j];
        sWd[j]       = W_dense[j];
        sWd[128 + j] = W_dense[128 + j];
    }
    for (int idx = tid; idx < HBUF; idx += NT) hcat[idx] = 0u;   // buffer 0 zeroed
    if (tid < BC) sBit[tid] = 2;
    __syncthreads();

    // ldmatrix per-lane A address base (buffer 0)
    const uint32_t hb0 = smem_u32(hcat)
        + (uint32_t)(((lane & 7) + ((lane >> 3) & 1) * 8) * HLD) * 4u
        + (uint32_t)(((lane >> 4) & 1) * 16);
    const float bd0 = b_dense[0], bd1 = b_dense[1];
    float lp = 0.f;

    for (int t = 0; t < NSTEP; ++t) {
        const uint32_t rdoff = (uint32_t)(t & 1) * (HBUF * 4);
        const uint32_t wroff = (uint32_t)((t & 1) ^ 1) * (HBUF * 4);
        uint32_t* hcwm = hcat + ((t & 1) ^ 1) * HBUF;   // write buffer

        float s1 = 0.f;
        if (tid < BC) s1 = __ldg(&samples[(t * BATCH + gRow) * 2 + 1]);

        // ========== L0: acc0 = h0[rd] @ W_hh0^T (K=128, resident B) ==========
        float acc0[2][4][4];
#pragma unroll
        for (int mt = 0; mt < 2; ++mt)
#pragma unroll
            for (int nt = 0; nt < 4; ++nt)
#pragma unroll
                for (int i = 0; i < 4; ++i) acc0[mt][nt][i] = 0.f;

#pragma unroll
        for (int kt = 0; kt < 8; ++kt) {
#pragma unroll
            for (int mt = 0; mt < 2; ++mt) {
                uint32_t a[4];
                ldmA(a, hb0 + rdoff + (uint32_t)(mt * 16 * HLD * 4) + (uint32_t)(kt * 32));
#pragma unroll
                for (int nt = 0; nt < 4; ++nt)
                    mma16(acc0[mt][nt], a, w0[nt][kt]);
            }
        }

        // ========== L1a: acc1 = h1[rd] @ W_hh1^T (independent of epi0) ==========
        float acc1[2][4][4];
#pragma unroll
        for (int mt = 0; mt < 2; ++mt)
#pragma unroll
            for (int nt = 0; nt < 4; ++nt)
#pragma unroll
                for (int i = 0; i < 4; ++i) acc1[mt][nt][i] = 0.f;

#pragma unroll
        for (int kt = 0; kt < 8; ++kt) {
            uint32_t b[4][2];
#pragma unroll
            for (int nt = 0; nt < 4; ++nt) {
                const uint32_t* wp = wB1 + (32 * w + nt * 8 + g) * WLD + 64 + kt * 8 + tq;
                b[nt][0] = wp[0];
                b[nt][1] = wp[4];
            }
#pragma unroll
            for (int mt = 0; mt < 2; ++mt) {
                uint32_t a[4];
                ldmA(a, hb0 + rdoff + 256u + (uint32_t)(kt * 32)
                        + (uint32_t)(mt * 16 * HLD * 4));
#pragma unroll
                for (int nt = 0; nt < 4; ++nt)
                    mma16(acc1[mt][nt], a, b[nt]);
            }
        }

        // join point: warp0's dense(t-1) sBit writes become visible here
        BAR_SYNC(1);

        // ---- epilogue0: h0' = tanh(acc0 + bias + onehot) -> h0[wr] ----
#pragma unroll
        for (int mt = 0; mt < 2; ++mt)
#pragma unroll
            for (int hh = 0; hh < 2; ++hh) {
                const int row = mt * 16 + g + hh * 8;
                const int bit = sBit[row];
                const float* cs = scTab + bit * 128;
#pragma unroll
                for (int nt = 0; nt < 4; ++nt) {
                    const int jc = 32 * w + nt * 8 + 2 * tq;
                    float v0 = acc0[mt][nt][hh * 2]     + cs[jc];
                    float v1 = acc0[mt][nt][hh * 2 + 1] + cs[jc + 1];
                    hcwm[row * HLD + 16 * w + nt * 4 + tq] =
                        pk_bf(tanh_fast(v0), tanh_fast(v1));
                }
            }
        __syncthreads();   // h0'[wr] visible to all warps

        // ========== L1b: acc1 += h0'[wr] @ W_ih1^T (short post-sync path) ==========
#pragma unroll
        for (int kt = 0; kt < 8; ++kt) {
            uint32_t b[4][2];
#pragma unroll
            for (int nt = 0; nt < 4; ++nt) {
                const uint32_t* wp = wB1 + (32 * w + nt * 8 + g) * WLD + kt * 8 + tq;
                b[nt][0] = wp[0];
                b[nt][1] = wp[4];
            }
#pragma unroll
            for (int mt = 0; mt < 2; ++mt) {
                uint32_t a[4];
                ldmA(a, hb0 + wroff + (uint32_t)(kt * 32)
                        + (uint32_t)(mt * 16 * HLD * 4));
#pragma unroll
                for (int nt = 0; nt < 4; ++nt)
                    mma16(acc1[mt][nt], a, b[nt]);
            }
        }

        // ---- epilogue1: h1' = tanh(acc1 + b1) -> h1[wr]; dense partials ----
#pragma unroll
        for (int mt = 0; mt < 2; ++mt)
#pragma unroll
            for (int hh = 0; hh < 2; ++hh) {
                const int row = mt * 16 + g + hh * 8;
                float q0 = 0.f, q1 = 0.f;
#pragma unroll
                for (int nt = 0; nt < 4; ++nt) {
                    const int jc = 32 * w + nt * 8 + 2 * tq;
                    float v0 = acc1[mt][nt][hh * 2]     + sB1v[jc];
                    float v1 = acc1[mt][nt][hh * 2 + 1] + sB1v[jc + 1];
                    float t0 = tanh_fast(v0), t1 = tanh_fast(v1);
                    q0 = fmaf(t0, sWd[jc], fmaf(t1, sWd[jc + 1], q0));
                    q1 = fmaf(t0, sWd[128 + jc], fmaf(t1, sWd[128 + jc + 1], q1));
                    hcwm[row * HLD + 64 + 16 * w + nt * 4 + tq] = pk_bf(t0, t1);
                }
                q0 += __shfl_xor_sync(0xffffffffu, q0, 1);
                q0 += __shfl_xor_sync(0xffffffffu, q0, 2);
                q1 += __shfl_xor_sync(0xffffffffu, q1, 1);
                q1 += __shfl_xor_sync(0xffffffffu, q1, 2);
                if (tq == 0) {
                    sPart[w * 64 + row]      = q0;
                    sPart[w * 64 + 32 + row] = q1;
                }
            }

        // ---- dense tail: only warp 0 blocks; warps 1-3 run ahead into L0/L1a(t+1) ----
        if (w == 0) {
            BAR_SYNC(2);        // wait for all sPart writes
            float L0 = bd0, L1 = bd1;
#pragma unroll
            for (int ww = 0; ww < 4; ++ww) {
                L0 += sPart[ww * 64 + lane];
                L1 += sPart[ww * 64 + 32 + lane];
            }
            float m = fmaxf(L0, L1);
            float lse = m + __logf(__expf(L0 - m) + __expf(L1 - m));
            int bit = (s1 > 0.5f) ? 1 : 0;
            lp += (bit ? L1 : L0) - lse;
            sBit[lane] = bit;
        } else {
            BAR_ARRIVE(2);
        }
    }

    if (tid < BC) out[gRow] = lp;
}

extern "C" void kernel_launch(void* const* d_in, const int* in_sizes, int n_in,
                              void* d_out, int out_size) {
    (void)in_sizes; (void)n_in; (void)out_size;
    cudaFuncSetAttribute(rnn_bf16s_kernel,
                         cudaFuncAttributeMaxDynamicSharedMemorySize, SMEM_BYTES);
    rnn_bf16s_kernel<<<BATCH / BC, NT, SMEM_BYTES>>>(
        (const float*)d_in[0],
        (const float*)d_in[1], (const float*)d_in[2],
        (const float*)d_in[3], (const float*)d_in[4],
        (const float*)d_in[5], (const float*)d_in[6],
        (const float*)d_in[7], (const float*)d_in[8],
        (const float*)d_in[9], (const float*)d_in[10],
        (float*)d_out);
}